// round 4
// baseline (speedup 1.0000x reference)
#include <cuda_runtime.h>
#include <math.h>
#include <stdint.h>

// Problem dims
#define NB 64
#define NS 64
#define NV 32000
#define NE 768
#define NH 1024
#define NHH 768

#define GRID 192
#define TPB  256

// ---------------- scratch (device globals; no allocations allowed) ----------
__device__ float g_X    [NB*NS*NE];            // LN'd embeddings, row = s*64+b
__device__ float g_IX   [(size_t)NB*NS*3*NH];  // x_t @ Wi_x + bi, per token
__device__ float g_ILraw[NB*3*NH];             // raw ILOW = IX_t + h_h @ Wi_h
__device__ float g_HG   [NB*3*NH];             // raw h_l @ Wh + bh
__device__ float g_IHI  [NB*3*NHH];            // raw h_l @ hWi + hbi
__device__ float g_HHG  [NB*3*NHH];            // raw h_h @ hWh + hbh
__device__ float2 g_psA [3*64*64];             // partial (sum,sumsq) stats
__device__ float2 g_psB [3*64*64];
__device__ float g_hl   [NB*NH];
__device__ float g_hh   [NB*NHH];
__device__ float g_HH   [NB*NS*NHH];           // h_h history, row = t*64+b

// grid barrier state (self-resetting; generation is monotonic across replays)
__device__ unsigned g_bar = 0;
__device__ volatile unsigned g_gen = 0;

// ---------------- init: zero hidden states ----------------------------------
__global__ void k_init() {
    int i = blockIdx.x * 256 + threadIdx.x;
    if (i < NB*NH)  g_hl[i] = 0.f;
    if (i < NB*NHH) g_hh[i] = 0.f;
}

// ---------------- embedding lookup + LayerNorm ------------------------------
__global__ void k_embed(const int* __restrict__ ids, const float* __restrict__ emb,
                        const float* __restrict__ g, const float* __restrict__ bb) {
    int tok = blockIdx.x;            // tok = s*64 + b
    int b = tok & 63, s = tok >> 6;
    int id = ids[b*NS + s];
    const float* e = emb + (size_t)id * NE;
    int tid = threadIdx.x;

    __shared__ float sa[256], sb[256];
    float sum = 0.f, sq = 0.f;
    for (int j = tid; j < NE; j += 256) { float v = e[j]; sum += v; sq += v*v; }
    sa[tid] = sum; sb[tid] = sq; __syncthreads();
    for (int o = 128; o > 0; o >>= 1) {
        if (tid < o) { sa[tid] += sa[tid+o]; sb[tid] += sb[tid+o]; }
        __syncthreads();
    }
    __shared__ float s_m, s_r;
    if (tid == 0) {
        float m = sa[0] / NE;
        float var = sb[0] / NE - m*m;
        s_m = m; s_r = rsqrtf(var + 1e-5f);
    }
    __syncthreads();
    float m = s_m, r = s_r;
    float* xo = g_X + (size_t)tok * NE;
    for (int j = tid; j < NE; j += 256) {
        float v = e[j];
        xo[j] = (v - m) * r * g[j] + bb[j];
    }
}

// ---------------- big GEMM: C[M,N] = A[M,K] @ W[K,N] + bias ------------------
__global__ void k_gemm_n64(const float* __restrict__ A, const float* __restrict__ W,
                           const float* __restrict__ bias, float* __restrict__ C,
                           int K, int N, int remap) {
    __shared__ float As[32][65];
    __shared__ float Ws[32][65];
    int tid = threadIdx.x;
    int tx = tid & 31, ty = tid >> 5;
    int n0 = blockIdx.x * 64;
    int m0 = blockIdx.y * 64;
    const float* Ab = A + (size_t)m0 * K;

    float acc[8][2];
    #pragma unroll
    for (int r = 0; r < 8; r++) { acc[r][0] = 0.f; acc[r][1] = 0.f; }

    for (int k0 = 0; k0 < K; k0 += 32) {
        #pragma unroll
        for (int i = 0; i < 8; i++) {
            int r = ty + i*8;
            As[tx][r] = Ab[(size_t)r*K + k0 + tx];
        }
        #pragma unroll
        for (int i = 0; i < 4; i++) {
            int kk = ty*4 + i;
            Ws[kk][tx]      = W[(size_t)(k0 + kk)*N + n0 + tx];
            Ws[kk][tx + 32] = W[(size_t)(k0 + kk)*N + n0 + tx + 32];
        }
        __syncthreads();
        #pragma unroll
        for (int k = 0; k < 32; k++) {
            float w0 = Ws[k][tx], w1 = Ws[k][tx + 32];
            #pragma unroll
            for (int r = 0; r < 8; r++) {
                float a = As[k][ty*8 + r];
                acc[r][0] += a * w0;
                acc[r][1] += a * w1;
            }
        }
        __syncthreads();
    }
    float b0 = bias ? bias[n0 + tx]      : 0.f;
    float b1 = bias ? bias[n0 + tx + 32] : 0.f;
    #pragma unroll
    for (int r = 0; r < 8; r++) {
        int grow = m0 + ty*8 + r;
        size_t orow = remap ? (size_t)((grow & 63) * 64 + (grow >> 6)) : (size_t)grow;
        C[orow*N + n0 + tx]      = acc[r][0] + b0;
        C[orow*N + n0 + tx + 32] = acc[r][1] + b1;
    }
}

// ================= persistent recurrence kernel ==============================

__device__ __forceinline__ void gridbar() {
    __syncthreads();
    if (threadIdx.x == 0) {
        __threadfence();
        unsigned g = g_gen;
        if (atomicAdd(&g_bar, 1u) == GRID - 1) {
            g_bar = 0;
            __threadfence();
            g_gen = g + 1;
        } else {
            while (g_gen == g) { __nanosleep(64); }
        }
        __threadfence();
    }
    __syncthreads();
}

// 64xN-tile GEMM: C[64,16] tile at col n0 = A[64,K] @ W[K, n0:n0+16] (+bias)(+Add)
// Also emits per-row (sum, sumsq) partials into pst[row*64] for LN stats.
__device__ __forceinline__ void gemm_tile(
    const float* __restrict__ A, int K,
    const float* __restrict__ W, int N,
    const float* __restrict__ bias, const float* __restrict__ Add,
    float* __restrict__ C, int n0,
    float2* __restrict__ pst,
    float* __restrict__ As /*[32*68]*/, float* __restrict__ Ws /*[32*17]*/)
{
    int tid = threadIdx.x;
    int col = tid & 15, rq = tid >> 4;
    int lk  = tid & 31, lr = tid >> 5;
    int wc  = tid & 15, wk = tid >> 4;

    float a0 = 0.f, a1 = 0.f, a2 = 0.f, a3 = 0.f;

    for (int k0 = 0; k0 < K; k0 += 32) {
        #pragma unroll
        for (int i = 0; i < 8; i++)
            As[lk*68 + lr + i*8] = A[(size_t)(lr + i*8)*K + k0 + lk];
        Ws[wk*17 + wc]        = W[(size_t)(k0 + wk     )*N + n0 + wc];
        Ws[(wk + 16)*17 + wc] = W[(size_t)(k0 + wk + 16)*N + n0 + wc];
        __syncthreads();
        #pragma unroll
        for (int k = 0; k < 32; k++) {
            float4 a = *reinterpret_cast<const float4*>(As + k*68 + rq*4);
            float w = Ws[k*17 + col];
            a0 += a.x*w; a1 += a.y*w; a2 += a.z*w; a3 += a.w*w;
        }
        __syncthreads();
    }
    float bv = bias ? bias[n0 + col] : 0.f;
    int r = rq * 4;
    float o0 = a0 + bv, o1 = a1 + bv, o2 = a2 + bv, o3 = a3 + bv;
    if (Add) {
        o0 += Add[(size_t)(r  )*N + n0 + col];
        o1 += Add[(size_t)(r+1)*N + n0 + col];
        o2 += Add[(size_t)(r+2)*N + n0 + col];
        o3 += Add[(size_t)(r+3)*N + n0 + col];
    }
    C[(size_t)(r  )*N + n0 + col] = o0;
    C[(size_t)(r+1)*N + n0 + col] = o1;
    C[(size_t)(r+2)*N + n0 + col] = o2;
    C[(size_t)(r+3)*N + n0 + col] = o3;

    // per-row partial stats across the 16 cols of this tile (lanes 0..15 groups)
    float q0 = o0*o0, q1 = o1*o1, q2 = o2*o2, q3 = o3*o3;
    #pragma unroll
    for (int off = 1; off < 16; off <<= 1) {
        o0 += __shfl_xor_sync(0xffffffffu, o0, off);
        q0 += __shfl_xor_sync(0xffffffffu, q0, off);
        o1 += __shfl_xor_sync(0xffffffffu, o1, off);
        q1 += __shfl_xor_sync(0xffffffffu, q1, off);
        o2 += __shfl_xor_sync(0xffffffffu, o2, off);
        q2 += __shfl_xor_sync(0xffffffffu, q2, off);
        o3 += __shfl_xor_sync(0xffffffffu, o3, off);
        q3 += __shfl_xor_sync(0xffffffffu, q3, off);
    }
    if (col == 0) {
        pst[(r  )*64] = make_float2(o0, q0);
        pst[(r+1)*64] = make_float2(o1, q1);
        pst[(r+2)*64] = make_float2(o2, q2);
        pst[(r+3)*64] = make_float2(o3, q3);
    }
}

// warp-cooperative stats finalize: sum T partials, return (mean, rstd)
__device__ __forceinline__ float2 warp_stat(const float2* __restrict__ p, int T, float inv_hid) {
    int l = threadIdx.x & 31;
    float s = p[l].x, q = p[l].y;
    if (l + 32 < T) { s += p[l+32].x; q += p[l+32].y; }
    #pragma unroll
    for (int o = 16; o > 0; o >>= 1) {
        s += __shfl_xor_sync(0xffffffffu, s, o);
        q += __shfl_xor_sync(0xffffffffu, q, o);
    }
    float m = s * inv_hid;
    float r = rsqrtf(q * inv_hid - m*m + 1e-5f);
    return make_float2(m, r);
}

__device__ __forceinline__ float sigm(float x) { return 1.f / (1.f + expf(-x)); }

__global__ void __launch_bounds__(TPB, 2) k_recur(
    const float* __restrict__ lWi, const float* __restrict__ lbh,
    const float* __restrict__ lWh,
    const float* __restrict__ llig, const float* __restrict__ llib,
    const float* __restrict__ llhg, const float* __restrict__ llhb,
    const float* __restrict__ hWi,  const float* __restrict__ hbi,
    const float* __restrict__ hWh,  const float* __restrict__ hbh,
    const float* __restrict__ hlig, const float* __restrict__ hlib,
    const float* __restrict__ hlhg, const float* __restrict__ hlhb)
{
    __shared__ __align__(16) float As[32*68];
    __shared__ float Ws[32*17];
    __shared__ float s_st[12];

    const float* lWi_h = lWi + (size_t)NE * 3 * NH;  // rows 768..1535 of low_Wi
    int bid = blockIdx.x, tid = threadIdx.x;
    int w = tid >> 5;
    int b = bid & 63, third = bid >> 6;

    for (int t = 0; t < NS; t++) {
        const float* ixt = g_IX + (size_t)t * NB * 3 * NH;
        for (int c = 0; c < 3; c++) {
            // ---- P1: ILOW = h_h @ Wi_h + IX_t  (raw + stats into psA) -------
            gemm_tile(g_hh, NHH, lWi_h, 3*NH, nullptr, ixt,
                      g_ILraw, bid*16, g_psA + (bid>>6)*4096 + (bid & 63), As, Ws);
            gridbar();

            // ---- low-cell inner loop ----------------------------------------
            for (int u = 0; u < 5; u++) {
                // HG = h_l @ Wh + bh (raw + stats into psB)
                gemm_tile(g_hl, NH, lWh, 3*NH, lbh, nullptr,
                          g_HG, bid*16, g_psB + (bid>>6)*4096 + (bid & 63), As, Ws);
                gridbar();

                // combine: LN(IL) + LN(HG) + gates -> h_l
                if (w < 6) {
                    const float2* p = (w < 3)
                        ? g_psA + w*4096 + b*64
                        : g_psB + (w-3)*4096 + b*64;
                    float2 mr = warp_stat(p, 64, 1.f/NH);
                    if ((tid & 31) == 0) { s_st[2*w] = mr.x; s_st[2*w+1] = mr.y; }
                }
                __syncthreads();
                {
                    const float* Ib = g_ILraw + (size_t)b*3*NH;
                    const float* Hb = g_HG    + (size_t)b*3*NH;
                    int js = (third * NH) / 3, je = ((third + 1) * NH) / 3;
                    for (int j = js + tid; j < je; j += TPB) {
                        float i0 = (Ib[j       ] - s_st[0])*s_st[1]*llig[j       ] + llib[j       ];
                        float i1 = (Ib[NH  + j ] - s_st[2])*s_st[3]*llig[NH  + j ] + llib[NH  + j ];
                        float i2 = (Ib[2*NH + j] - s_st[4])*s_st[5]*llig[2*NH + j] + llib[2*NH + j];
                        float h0 = (Hb[j       ] - s_st[6])*s_st[7]*llhg[j       ] + llhb[j       ];
                        float h1 = (Hb[NH  + j ] - s_st[8])*s_st[9]*llhg[NH  + j ] + llhb[NH  + j ];
                        float h2 = (Hb[2*NH + j] - s_st[10])*s_st[11]*llhg[2*NH + j] + llhb[2*NH + j];
                        float r = sigm(i0 + h0);
                        float z = sigm(i1 + h1);
                        float n = tanhf(i2 + r*h2);
                        float hp = g_hl[(size_t)b*NH + j];
                        g_hl[(size_t)b*NH + j] = (1.f - z)*n + z*hp;
                    }
                }
                gridbar();
            }

            // ---- P5: high-cell GEMMs (288 tile jobs over 192 blocks) --------
            for (int job = bid; job < 288; job += GRID) {
                if (job < 144) {
                    gemm_tile(g_hl, NH, hWi, 3*NHH, hbi, nullptr,
                              g_IHI, job*16, g_psA + (job/48)*4096 + (job%48), As, Ws);
                } else {
                    int nt = job - 144;
                    gemm_tile(g_hh, NHH, hWh, 3*NHH, hbh, nullptr,
                              g_HHG, nt*16, g_psB + (nt/48)*4096 + (nt%48), As, Ws);
                }
            }
            gridbar();

            // ---- P6: high combine -> h_h (+history at c==2) ------------------
            if (w < 6) {
                const float2* p = (w < 3)
                    ? g_psA + w*4096 + b*64
                    : g_psB + (w-3)*4096 + b*64;
                float2 mr = warp_stat(p, 48, 1.f/NHH);
                if ((tid & 31) == 0) { s_st[2*w] = mr.x; s_st[2*w+1] = mr.y; }
            }
            __syncthreads();
            {
                const float* Ib = g_IHI + (size_t)b*3*NHH;
                const float* Hb = g_HHG + (size_t)b*3*NHH;
                int j = third*256 + tid;   // exactly covers 0..767
                float i0 = (Ib[j        ] - s_st[0])*s_st[1]*hlig[j        ] + hlib[j        ];
                float i1 = (Ib[NHH  + j ] - s_st[2])*s_st[3]*hlig[NHH  + j ] + hlib[NHH  + j ];
                float i2 = (Ib[2*NHH + j] - s_st[4])*s_st[5]*hlig[2*NHH + j] + hlib[2*NHH + j];
                float h0 = (Hb[j        ] - s_st[6])*s_st[7]*hlhg[j        ] + hlhb[j        ];
                float h1 = (Hb[NHH  + j ] - s_st[8])*s_st[9]*hlhg[NHH  + j ] + hlhb[NHH  + j ];
                float h2 = (Hb[2*NHH + j] - s_st[10])*s_st[11]*hlhg[2*NHH + j] + hlhb[2*NHH + j];
                float r = sigm(i0 + h0);
                float z = sigm(i1 + h1);
                float n = tanhf(i2 + r*h2);
                float hp = g_hh[(size_t)b*NHH + j];
                float nv = (1.f - z)*n + z*hp;
                g_hh[(size_t)b*NHH + j] = nv;
                if (c == 2) g_HH[(size_t)(t*64 + b)*NHH + j] = nv;
            }
            gridbar();
        }
    }
}

// ---------------- host orchestration ----------------------------------------
extern "C" void kernel_launch(void* const* d_in, const int* in_sizes, int n_in,
                              void* d_out, int out_size) {
    const int*   ids  = (const int*)  d_in[0];
    const float* emb  = (const float*)d_in[1];
    const float* leg  = (const float*)d_in[2];
    const float* leb  = (const float*)d_in[3];
    const float* lWi  = (const float*)d_in[4];   // [1536, 3072]
    const float* lbi  = (const float*)d_in[5];
    const float* lWh  = (const float*)d_in[6];   // [1024, 3072]
    const float* lbh  = (const float*)d_in[7];
    const float* llig = (const float*)d_in[8];
    const float* llib = (const float*)d_in[9];
    const float* llhg = (const float*)d_in[10];
    const float* llhb = (const float*)d_in[11];
    const float* hWi  = (const float*)d_in[12];  // [1024, 2304]
    const float* hbi  = (const float*)d_in[13];
    const float* hWh  = (const float*)d_in[14];  // [768, 2304]
    const float* hbh  = (const float*)d_in[15];
    const float* hlig = (const float*)d_in[16];
    const float* hlib = (const float*)d_in[17];
    const float* hlhg = (const float*)d_in[18];
    const float* hlhb = (const float*)d_in[19];
    const float* Wout = (const float*)d_in[20];  // [768, 32000]
    const float* bout = (const float*)d_in[21];
    float* out = (float*)d_out;

    float *pX, *pIX, *pHH;
    cudaGetSymbolAddress((void**)&pX,  g_X);
    cudaGetSymbolAddress((void**)&pIX, g_IX);
    cudaGetSymbolAddress((void**)&pHH, g_HH);

    // zero hidden states
    k_init<<<256, 256>>>();

    // x = LN(emb[ids]) laid out [S, B, E]
    k_embed<<<NB*NS, 256>>>(ids, emb, leg, leb);

    // IX = x @ Wi_x + bi for ALL tokens up front (reused 15x per step)
    k_gemm_n64<<<dim3((3*NH)/64, (NB*NS)/64), 256>>>(pX, lWi, lbi, pIX, NE, 3*NH, 0);

    // full recurrence in ONE persistent kernel (software grid barriers)
    k_recur<<<GRID, TPB>>>(lWi, lbh, lWh,
                           llig, llib, llhg, llhb,
                           hWi, hbi, hWh, hbh,
                           hlig, hlib, hlhg, hlhb);

    // logits = h_h_hist @ Wout + bout, row remap (s*64+b) -> out[(b*64+s)*V]
    k_gemm_n64<<<dim3(NV/64, (NB*NS)/64), 256>>>(pHH, Wout, bout, out, NHH, NV, 1);
}

// round 5
// speedup vs baseline: 1.0000x; 1.0000x over previous
#include <cuda_runtime.h>
#include <math.h>
#include <stdint.h>

// Problem dims
#define NB 64
#define NS 64
#define NV 32000
#define NE 768
#define NH 1024
#define NHH 768

#define GRID 192
#define TPB  256

// ---------------- scratch (device globals; no allocations allowed) ----------
__device__ float g_X    [NB*NS*NE];            // LN'd embeddings, row = s*64+b
__device__ float g_IX   [(size_t)NB*NS*3*NH];  // x_t @ Wi_x + bi, per token
__device__ float g_ILraw[NB*3*NH];             // raw ILOW = IX_t + h_h @ Wi_h
__device__ float g_HG   [NB*3*NH];             // raw h_l @ Wh + bh
__device__ float g_IHI  [NB*3*NHH];            // raw h_l @ hWi + hbi
__device__ float g_HHG  [NB*3*NHH];            // raw h_h @ hWh + hbh
__device__ float2 g_psA [3*64*64];             // partial (sum,sumsq) stats
__device__ float2 g_psB [3*64*64];
__device__ float g_hl   [NB*NH];
__device__ float g_hh   [NB*NHH];
__device__ float g_HH   [NB*NS*NHH];           // h_h history, row = t*64+b

// grid barrier state (self-resetting; generation is monotonic across replays)
__device__ unsigned g_bar = 0;
__device__ volatile unsigned g_gen = 0;

// ---------------- init: zero hidden states ----------------------------------
__global__ void k_init() {
    int i = blockIdx.x * 256 + threadIdx.x;
    if (i < NB*NH)  g_hl[i] = 0.f;
    if (i < NB*NHH) g_hh[i] = 0.f;
}

// ---------------- embedding lookup + LayerNorm ------------------------------
__global__ void k_embed(const int* __restrict__ ids, const float* __restrict__ emb,
                        const float* __restrict__ g, const float* __restrict__ bb) {
    int tok = blockIdx.x;            // tok = s*64 + b
    int b = tok & 63, s = tok >> 6;
    int id = ids[b*NS + s];
    const float* e = emb + (size_t)id * NE;
    int tid = threadIdx.x;

    __shared__ float sa[256], sb[256];
    float sum = 0.f, sq = 0.f;
    for (int j = tid; j < NE; j += 256) { float v = e[j]; sum += v; sq += v*v; }
    sa[tid] = sum; sb[tid] = sq; __syncthreads();
    for (int o = 128; o > 0; o >>= 1) {
        if (tid < o) { sa[tid] += sa[tid+o]; sb[tid] += sb[tid+o]; }
        __syncthreads();
    }
    __shared__ float s_m, s_r;
    if (tid == 0) {
        float m = sa[0] / NE;
        float var = sb[0] / NE - m*m;
        s_m = m; s_r = rsqrtf(var + 1e-5f);
    }
    __syncthreads();
    float m = s_m, r = s_r;
    float* xo = g_X + (size_t)tok * NE;
    for (int j = tid; j < NE; j += 256) {
        float v = e[j];
        xo[j] = (v - m) * r * g[j] + bb[j];
    }
}

// ---------------- big GEMM: C[M,N] = A[M,K] @ W[K,N] + bias ------------------
__global__ void k_gemm_n64(const float* __restrict__ A, const float* __restrict__ W,
                           const float* __restrict__ bias, float* __restrict__ C,
                           int K, int N, int remap) {
    __shared__ float As[32][65];
    __shared__ float Ws[32][65];
    int tid = threadIdx.x;
    int tx = tid & 31, ty = tid >> 5;
    int n0 = blockIdx.x * 64;
    int m0 = blockIdx.y * 64;
    const float* Ab = A + (size_t)m0 * K;

    float acc[8][2];
    #pragma unroll
    for (int r = 0; r < 8; r++) { acc[r][0] = 0.f; acc[r][1] = 0.f; }

    for (int k0 = 0; k0 < K; k0 += 32) {
        #pragma unroll
        for (int i = 0; i < 8; i++) {
            int r = ty + i*8;
            As[tx][r] = Ab[(size_t)r*K + k0 + tx];
        }
        #pragma unroll
        for (int i = 0; i < 4; i++) {
            int kk = ty*4 + i;
            Ws[kk][tx]      = W[(size_t)(k0 + kk)*N + n0 + tx];
            Ws[kk][tx + 32] = W[(size_t)(k0 + kk)*N + n0 + tx + 32];
        }
        __syncthreads();
        #pragma unroll
        for (int k = 0; k < 32; k++) {
            float w0 = Ws[k][tx], w1 = Ws[k][tx + 32];
            #pragma unroll
            for (int r = 0; r < 8; r++) {
                float a = As[k][ty*8 + r];
                acc[r][0] += a * w0;
                acc[r][1] += a * w1;
            }
        }
        __syncthreads();
    }
    float b0 = bias ? bias[n0 + tx]      : 0.f;
    float b1 = bias ? bias[n0 + tx + 32] : 0.f;
    #pragma unroll
    for (int r = 0; r < 8; r++) {
        int grow = m0 + ty*8 + r;
        size_t orow = remap ? (size_t)((grow & 63) * 64 + (grow >> 6)) : (size_t)grow;
        C[orow*N + n0 + tx]      = acc[r][0] + b0;
        C[orow*N + n0 + tx + 32] = acc[r][1] + b1;
    }
}

// ================= persistent recurrence kernel ==============================

__device__ __forceinline__ void gridbar() {
    __syncthreads();
    if (threadIdx.x == 0) {
        __threadfence();
        unsigned g = g_gen;
        if (atomicAdd(&g_bar, 1u) == GRID - 1) {
            g_bar = 0;
            __threadfence();
            g_gen = g + 1;
        } else {
            while (g_gen == g) { __nanosleep(64); }
        }
        __threadfence();
    }
    __syncthreads();
}

// 64xN-tile GEMM: C[64,16] tile at col n0 = A[64,K] @ W[K, n0:n0+16] (+bias)(+Add)
// Also emits per-row (sum, sumsq) partials into pst[row*64] for LN stats.
__device__ __forceinline__ void gemm_tile(
    const float* __restrict__ A, int K,
    const float* __restrict__ W, int N,
    const float* __restrict__ bias, const float* __restrict__ Add,
    float* __restrict__ C, int n0,
    float2* __restrict__ pst,
    float* __restrict__ As /*[32*68]*/, float* __restrict__ Ws /*[32*17]*/)
{
    int tid = threadIdx.x;
    int col = tid & 15, rq = tid >> 4;
    int lk  = tid & 31, lr = tid >> 5;
    int wc  = tid & 15, wk = tid >> 4;

    float a0 = 0.f, a1 = 0.f, a2 = 0.f, a3 = 0.f;

    for (int k0 = 0; k0 < K; k0 += 32) {
        #pragma unroll
        for (int i = 0; i < 8; i++)
            As[lk*68 + lr + i*8] = A[(size_t)(lr + i*8)*K + k0 + lk];
        Ws[wk*17 + wc]        = W[(size_t)(k0 + wk     )*N + n0 + wc];
        Ws[(wk + 16)*17 + wc] = W[(size_t)(k0 + wk + 16)*N + n0 + wc];
        __syncthreads();
        #pragma unroll
        for (int k = 0; k < 32; k++) {
            float4 a = *reinterpret_cast<const float4*>(As + k*68 + rq*4);
            float w = Ws[k*17 + col];
            a0 += a.x*w; a1 += a.y*w; a2 += a.z*w; a3 += a.w*w;
        }
        __syncthreads();
    }
    float bv = bias ? bias[n0 + col] : 0.f;
    int r = rq * 4;
    float o0 = a0 + bv, o1 = a1 + bv, o2 = a2 + bv, o3 = a3 + bv;
    if (Add) {
        o0 += Add[(size_t)(r  )*N + n0 + col];
        o1 += Add[(size_t)(r+1)*N + n0 + col];
        o2 += Add[(size_t)(r+2)*N + n0 + col];
        o3 += Add[(size_t)(r+3)*N + n0 + col];
    }
    C[(size_t)(r  )*N + n0 + col] = o0;
    C[(size_t)(r+1)*N + n0 + col] = o1;
    C[(size_t)(r+2)*N + n0 + col] = o2;
    C[(size_t)(r+3)*N + n0 + col] = o3;

    // per-row partial stats across the 16 cols of this tile (lanes 0..15 groups)
    float q0 = o0*o0, q1 = o1*o1, q2 = o2*o2, q3 = o3*o3;
    #pragma unroll
    for (int off = 1; off < 16; off <<= 1) {
        o0 += __shfl_xor_sync(0xffffffffu, o0, off);
        q0 += __shfl_xor_sync(0xffffffffu, q0, off);
        o1 += __shfl_xor_sync(0xffffffffu, o1, off);
        q1 += __shfl_xor_sync(0xffffffffu, q1, off);
        o2 += __shfl_xor_sync(0xffffffffu, o2, off);
        q2 += __shfl_xor_sync(0xffffffffu, q2, off);
        o3 += __shfl_xor_sync(0xffffffffu, o3, off);
        q3 += __shfl_xor_sync(0xffffffffu, q3, off);
    }
    if (col == 0) {
        pst[(r  )*64] = make_float2(o0, q0);
        pst[(r+1)*64] = make_float2(o1, q1);
        pst[(r+2)*64] = make_float2(o2, q2);
        pst[(r+3)*64] = make_float2(o3, q3);
    }
}

// warp-cooperative stats finalize: sum T partials, return (mean, rstd)
__device__ __forceinline__ float2 warp_stat(const float2* __restrict__ p, int T, float inv_hid) {
    int l = threadIdx.x & 31;
    float s = p[l].x, q = p[l].y;
    if (l + 32 < T) { s += p[l+32].x; q += p[l+32].y; }
    #pragma unroll
    for (int o = 16; o > 0; o >>= 1) {
        s += __shfl_xor_sync(0xffffffffu, s, o);
        q += __shfl_xor_sync(0xffffffffu, q, o);
    }
    float m = s * inv_hid;
    float r = rsqrtf(q * inv_hid - m*m + 1e-5f);
    return make_float2(m, r);
}

__device__ __forceinline__ float sigm(float x) { return 1.f / (1.f + expf(-x)); }

__global__ void __launch_bounds__(TPB, 2) k_recur(
    const float* __restrict__ lWi, const float* __restrict__ lbh,
    const float* __restrict__ lWh,
    const float* __restrict__ llig, const float* __restrict__ llib,
    const float* __restrict__ llhg, const float* __restrict__ llhb,
    const float* __restrict__ hWi,  const float* __restrict__ hbi,
    const float* __restrict__ hWh,  const float* __restrict__ hbh,
    const float* __restrict__ hlig, const float* __restrict__ hlib,
    const float* __restrict__ hlhg, const float* __restrict__ hlhb)
{
    __shared__ __align__(16) float As[32*68];
    __shared__ float Ws[32*17];
    __shared__ float s_st[12];

    const float* lWi_h = lWi + (size_t)NE * 3 * NH;  // rows 768..1535 of low_Wi
    int bid = blockIdx.x, tid = threadIdx.x;
    int w = tid >> 5;
    int b = bid & 63, third = bid >> 6;

    for (int t = 0; t < NS; t++) {
        const float* ixt = g_IX + (size_t)t * NB * 3 * NH;
        for (int c = 0; c < 3; c++) {
            // ---- P1: ILOW = h_h @ Wi_h + IX_t  (raw + stats into psA) -------
            gemm_tile(g_hh, NHH, lWi_h, 3*NH, nullptr, ixt,
                      g_ILraw, bid*16, g_psA + (bid>>6)*4096 + (bid & 63), As, Ws);
            gridbar();

            // ---- low-cell inner loop ----------------------------------------
            for (int u = 0; u < 5; u++) {
                // HG = h_l @ Wh + bh (raw + stats into psB)
                gemm_tile(g_hl, NH, lWh, 3*NH, lbh, nullptr,
                          g_HG, bid*16, g_psB + (bid>>6)*4096 + (bid & 63), As, Ws);
                gridbar();

                // combine: LN(IL) + LN(HG) + gates -> h_l
                if (w < 6) {
                    const float2* p = (w < 3)
                        ? g_psA + w*4096 + b*64
                        : g_psB + (w-3)*4096 + b*64;
                    float2 mr = warp_stat(p, 64, 1.f/NH);
                    if ((tid & 31) == 0) { s_st[2*w] = mr.x; s_st[2*w+1] = mr.y; }
                }
                __syncthreads();
                {
                    const float* Ib = g_ILraw + (size_t)b*3*NH;
                    const float* Hb = g_HG    + (size_t)b*3*NH;
                    int js = (third * NH) / 3, je = ((third + 1) * NH) / 3;
                    for (int j = js + tid; j < je; j += TPB) {
                        float i0 = (Ib[j       ] - s_st[0])*s_st[1]*llig[j       ] + llib[j       ];
                        float i1 = (Ib[NH  + j ] - s_st[2])*s_st[3]*llig[NH  + j ] + llib[NH  + j ];
                        float i2 = (Ib[2*NH + j] - s_st[4])*s_st[5]*llig[2*NH + j] + llib[2*NH + j];
                        float h0 = (Hb[j       ] - s_st[6])*s_st[7]*llhg[j       ] + llhb[j       ];
                        float h1 = (Hb[NH  + j ] - s_st[8])*s_st[9]*llhg[NH  + j ] + llhb[NH  + j ];
                        float h2 = (Hb[2*NH + j] - s_st[10])*s_st[11]*llhg[2*NH + j] + llhb[2*NH + j];
                        float r = sigm(i0 + h0);
                        float z = sigm(i1 + h1);
                        float n = tanhf(i2 + r*h2);
                        float hp = g_hl[(size_t)b*NH + j];
                        g_hl[(size_t)b*NH + j] = (1.f - z)*n + z*hp;
                    }
                }
                gridbar();
            }

            // ---- P5: high-cell GEMMs (288 tile jobs over 192 blocks) --------
            for (int job = bid; job < 288; job += GRID) {
                if (job < 144) {
                    gemm_tile(g_hl, NH, hWi, 3*NHH, hbi, nullptr,
                              g_IHI, job*16, g_psA + (job/48)*4096 + (job%48), As, Ws);
                } else {
                    int nt = job - 144;
                    gemm_tile(g_hh, NHH, hWh, 3*NHH, hbh, nullptr,
                              g_HHG, nt*16, g_psB + (nt/48)*4096 + (nt%48), As, Ws);
                }
            }
            gridbar();

            // ---- P6: high combine -> h_h (+history at c==2) ------------------
            if (w < 6) {
                const float2* p = (w < 3)
                    ? g_psA + w*4096 + b*64
                    : g_psB + (w-3)*4096 + b*64;
                float2 mr = warp_stat(p, 48, 1.f/NHH);
                if ((tid & 31) == 0) { s_st[2*w] = mr.x; s_st[2*w+1] = mr.y; }
            }
            __syncthreads();
            {
                const float* Ib = g_IHI + (size_t)b*3*NHH;
                const float* Hb = g_HHG + (size_t)b*3*NHH;
                int j = third*256 + tid;   // exactly covers 0..767
                float i0 = (Ib[j        ] - s_st[0])*s_st[1]*hlig[j        ] + hlib[j        ];
                float i1 = (Ib[NHH  + j ] - s_st[2])*s_st[3]*hlig[NHH  + j ] + hlib[NHH  + j ];
                float i2 = (Ib[2*NHH + j] - s_st[4])*s_st[5]*hlig[2*NHH + j] + hlib[2*NHH + j];
                float h0 = (Hb[j        ] - s_st[6])*s_st[7]*hlhg[j        ] + hlhb[j        ];
                float h1 = (Hb[NHH  + j ] - s_st[8])*s_st[9]*hlhg[NHH  + j ] + hlhb[NHH  + j ];
                float h2 = (Hb[2*NHH + j] - s_st[10])*s_st[11]*hlhg[2*NHH + j] + hlhb[2*NHH + j];
                float r = sigm(i0 + h0);
                float z = sigm(i1 + h1);
                float n = tanhf(i2 + r*h2);
                float hp = g_hh[(size_t)b*NHH + j];
                float nv = (1.f - z)*n + z*hp;
                g_hh[(size_t)b*NHH + j] = nv;
                if (c == 2) g_HH[(size_t)(t*64 + b)*NHH + j] = nv;
            }
            gridbar();
        }
    }
}

// ---------------- host orchestration ----------------------------------------
extern "C" void kernel_launch(void* const* d_in, const int* in_sizes, int n_in,
                              void* d_out, int out_size) {
    const int*   ids  = (const int*)  d_in[0];
    const float* emb  = (const float*)d_in[1];
    const float* leg  = (const float*)d_in[2];
    const float* leb  = (const float*)d_in[3];
    const float* lWi  = (const float*)d_in[4];   // [1536, 3072]
    const float* lbi  = (const float*)d_in[5];
    const float* lWh  = (const float*)d_in[6];   // [1024, 3072]
    const float* lbh  = (const float*)d_in[7];
    const float* llig = (const float*)d_in[8];
    const float* llib = (const float*)d_in[9];
    const float* llhg = (const float*)d_in[10];
    const float* llhb = (const float*)d_in[11];
    const float* hWi  = (const float*)d_in[12];  // [1024, 2304]
    const float* hbi  = (const float*)d_in[13];
    const float* hWh  = (const float*)d_in[14];  // [768, 2304]
    const float* hbh  = (const float*)d_in[15];
    const float* hlig = (const float*)d_in[16];
    const float* hlib = (const float*)d_in[17];
    const float* hlhg = (const float*)d_in[18];
    const float* hlhb = (const float*)d_in[19];
    const float* Wout = (const float*)d_in[20];  // [768, 32000]
    const float* bout = (const float*)d_in[21];
    float* out = (float*)d_out;

    float *pX, *pIX, *pHH;
    cudaGetSymbolAddress((void**)&pX,  g_X);
    cudaGetSymbolAddress((void**)&pIX, g_IX);
    cudaGetSymbolAddress((void**)&pHH, g_HH);

    // zero hidden states
    k_init<<<256, 256>>>();

    // x = LN(emb[ids]) laid out [S, B, E]
    k_embed<<<NB*NS, 256>>>(ids, emb, leg, leb);

    // IX = x @ Wi_x + bi for ALL tokens up front (reused 15x per step)
    k_gemm_n64<<<dim3((3*NH)/64, (NB*NS)/64), 256>>>(pX, lWi, lbi, pIX, NE, 3*NH, 0);

    // full recurrence in ONE persistent kernel (software grid barriers)
    k_recur<<<GRID, TPB>>>(lWi, lbh, lWh,
                           llig, llib, llhg, llhb,
                           hWi, hbi, hWh, hbh,
                           hlig, hlib, hlhg, hlhb);

    // logits = h_h_hist @ Wout + bout, row remap (s*64+b) -> out[(b*64+s)*V]
    k_gemm_n64<<<dim3(NV/64, (NB*NS)/64), 256>>>(pHH, Wout, bout, out, NHH, NV, 1);
}

// round 6
// speedup vs baseline: 1.0059x; 1.0059x over previous
#include <cuda_runtime.h>
#include <math.h>
#include <stdint.h>

// Problem dims
#define NB 64
#define NS 64
#define NV 32000
#define NE 768
#define NH 1024
#define NHH 768

#define GRID 192
#define TPB  256

// ---------------- scratch (device globals; no allocations allowed) ----------
__device__ float g_X    [NB*NS*NE];            // LN'd embeddings, row = s*64+b
__device__ float g_IX   [(size_t)NB*NS*3*NH];  // x_t @ Wi_x + bi, per token
__device__ float g_ILraw[NB*3*NH];             // raw ILOW = IX_t + h_h @ Wi_h
__device__ float g_HG   [NB*3*NH];             // raw h_l @ Wh + bh
__device__ float g_IHI  [NB*3*NHH];            // raw h_l @ hWi + hbi
__device__ float g_HHG  [NB*3*NHH];            // raw h_h @ hWh + hbh
__device__ float2 g_psA [3*64*64];             // partial (sum,sumsq) stats
__device__ float2 g_psB [3*64*64];
__device__ float g_hl   [NB*NH];
__device__ float g_hh   [NB*NHH];
__device__ float g_HH   [NB*NS*NHH];           // h_h history, row = t*64+b

// grid barrier state (self-resetting; generation is monotonic across replays)
__device__ unsigned g_bar = 0;
__device__ volatile unsigned g_gen = 0;

// ---------------- init: zero hidden states ----------------------------------
__global__ void k_init() {
    int i = blockIdx.x * 256 + threadIdx.x;
    if (i < NB*NH)  g_hl[i] = 0.f;
    if (i < NB*NHH) g_hh[i] = 0.f;
}

// ---------------- embedding lookup + LayerNorm ------------------------------
__global__ void k_embed(const int* __restrict__ ids, const float* __restrict__ emb,
                        const float* __restrict__ g, const float* __restrict__ bb) {
    int tok = blockIdx.x;            // tok = s*64 + b
    int b = tok & 63, s = tok >> 6;
    int id = ids[b*NS + s];
    const float* e = emb + (size_t)id * NE;
    int tid = threadIdx.x;

    __shared__ float sa[256], sb[256];
    float sum = 0.f, sq = 0.f;
    for (int j = tid; j < NE; j += 256) { float v = e[j]; sum += v; sq += v*v; }
    sa[tid] = sum; sb[tid] = sq; __syncthreads();
    for (int o = 128; o > 0; o >>= 1) {
        if (tid < o) { sa[tid] += sa[tid+o]; sb[tid] += sb[tid+o]; }
        __syncthreads();
    }
    __shared__ float s_m, s_r;
    if (tid == 0) {
        float m = sa[0] / NE;
        float var = sb[0] / NE - m*m;
        s_m = m; s_r = rsqrtf(var + 1e-5f);
    }
    __syncthreads();
    float m = s_m, r = s_r;
    float* xo = g_X + (size_t)tok * NE;
    for (int j = tid; j < NE; j += 256) {
        float v = e[j];
        xo[j] = (v - m) * r * g[j] + bb[j];
    }
}

// ---------------- big GEMM: C[M,N] = A[M,K] @ W[K,N] + bias ------------------
__global__ void k_gemm_n64(const float* __restrict__ A, const float* __restrict__ W,
                           const float* __restrict__ bias, float* __restrict__ C,
                           int K, int N, int remap) {
    __shared__ float As[32][65];
    __shared__ float Ws[32][65];
    int tid = threadIdx.x;
    int tx = tid & 31, ty = tid >> 5;
    int n0 = blockIdx.x * 64;
    int m0 = blockIdx.y * 64;
    const float* Ab = A + (size_t)m0 * K;

    float acc[8][2];
    #pragma unroll
    for (int r = 0; r < 8; r++) { acc[r][0] = 0.f; acc[r][1] = 0.f; }

    for (int k0 = 0; k0 < K; k0 += 32) {
        #pragma unroll
        for (int i = 0; i < 8; i++) {
            int r = ty + i*8;
            As[tx][r] = Ab[(size_t)r*K + k0 + tx];
        }
        #pragma unroll
        for (int i = 0; i < 4; i++) {
            int kk = ty*4 + i;
            Ws[kk][tx]      = W[(size_t)(k0 + kk)*N + n0 + tx];
            Ws[kk][tx + 32] = W[(size_t)(k0 + kk)*N + n0 + tx + 32];
        }
        __syncthreads();
        #pragma unroll
        for (int k = 0; k < 32; k++) {
            float w0 = Ws[k][tx], w1 = Ws[k][tx + 32];
            #pragma unroll
            for (int r = 0; r < 8; r++) {
                float a = As[k][ty*8 + r];
                acc[r][0] += a * w0;
                acc[r][1] += a * w1;
            }
        }
        __syncthreads();
    }
    float b0 = bias ? bias[n0 + tx]      : 0.f;
    float b1 = bias ? bias[n0 + tx + 32] : 0.f;
    #pragma unroll
    for (int r = 0; r < 8; r++) {
        int grow = m0 + ty*8 + r;
        size_t orow = remap ? (size_t)((grow & 63) * 64 + (grow >> 6)) : (size_t)grow;
        C[orow*N + n0 + tx]      = acc[r][0] + b0;
        C[orow*N + n0 + tx + 32] = acc[r][1] + b1;
    }
}

// ================= persistent recurrence kernel ==============================

__device__ __forceinline__ void gridbar() {
    __syncthreads();
    if (threadIdx.x == 0) {
        __threadfence();
        unsigned g = g_gen;
        if (atomicAdd(&g_bar, 1u) == GRID - 1) {
            g_bar = 0;
            __threadfence();
            g_gen = g + 1;
        } else {
            while (g_gen == g) { __nanosleep(64); }
        }
        __threadfence();
    }
    __syncthreads();
}

// 64xN-tile GEMM: C[64,16] tile at col n0 = A[64,K] @ W[K, n0:n0+16] (+bias)(+Add)
// Also emits per-row (sum, sumsq) partials into pst[row*64] for LN stats.
__device__ __forceinline__ void gemm_tile(
    const float* __restrict__ A, int K,
    const float* __restrict__ W, int N,
    const float* __restrict__ bias, const float* __restrict__ Add,
    float* __restrict__ C, int n0,
    float2* __restrict__ pst,
    float* __restrict__ As /*[32*68]*/, float* __restrict__ Ws /*[32*17]*/)
{
    int tid = threadIdx.x;
    int col = tid & 15, rq = tid >> 4;
    int lk  = tid & 31, lr = tid >> 5;
    int wc  = tid & 15, wk = tid >> 4;

    float a0 = 0.f, a1 = 0.f, a2 = 0.f, a3 = 0.f;

    for (int k0 = 0; k0 < K; k0 += 32) {
        #pragma unroll
        for (int i = 0; i < 8; i++)
            As[lk*68 + lr + i*8] = A[(size_t)(lr + i*8)*K + k0 + lk];
        Ws[wk*17 + wc]        = W[(size_t)(k0 + wk     )*N + n0 + wc];
        Ws[(wk + 16)*17 + wc] = W[(size_t)(k0 + wk + 16)*N + n0 + wc];
        __syncthreads();
        #pragma unroll
        for (int k = 0; k < 32; k++) {
            float4 a = *reinterpret_cast<const float4*>(As + k*68 + rq*4);
            float w = Ws[k*17 + col];
            a0 += a.x*w; a1 += a.y*w; a2 += a.z*w; a3 += a.w*w;
        }
        __syncthreads();
    }
    float bv = bias ? bias[n0 + col] : 0.f;
    int r = rq * 4;
    float o0 = a0 + bv, o1 = a1 + bv, o2 = a2 + bv, o3 = a3 + bv;
    if (Add) {
        o0 += Add[(size_t)(r  )*N + n0 + col];
        o1 += Add[(size_t)(r+1)*N + n0 + col];
        o2 += Add[(size_t)(r+2)*N + n0 + col];
        o3 += Add[(size_t)(r+3)*N + n0 + col];
    }
    C[(size_t)(r  )*N + n0 + col] = o0;
    C[(size_t)(r+1)*N + n0 + col] = o1;
    C[(size_t)(r+2)*N + n0 + col] = o2;
    C[(size_t)(r+3)*N + n0 + col] = o3;

    // per-row partial stats across the 16 cols of this tile (lanes 0..15 groups)
    float q0 = o0*o0, q1 = o1*o1, q2 = o2*o2, q3 = o3*o3;
    #pragma unroll
    for (int off = 1; off < 16; off <<= 1) {
        o0 += __shfl_xor_sync(0xffffffffu, o0, off);
        q0 += __shfl_xor_sync(0xffffffffu, q0, off);
        o1 += __shfl_xor_sync(0xffffffffu, o1, off);
        q1 += __shfl_xor_sync(0xffffffffu, q1, off);
        o2 += __shfl_xor_sync(0xffffffffu, o2, off);
        q2 += __shfl_xor_sync(0xffffffffu, q2, off);
        o3 += __shfl_xor_sync(0xffffffffu, o3, off);
        q3 += __shfl_xor_sync(0xffffffffu, q3, off);
    }
    if (col == 0) {
        pst[(r  )*64] = make_float2(o0, q0);
        pst[(r+1)*64] = make_float2(o1, q1);
        pst[(r+2)*64] = make_float2(o2, q2);
        pst[(r+3)*64] = make_float2(o3, q3);
    }
}

// warp-cooperative stats finalize: sum T partials, return (mean, rstd)
__device__ __forceinline__ float2 warp_stat(const float2* __restrict__ p, int T, float inv_hid) {
    int l = threadIdx.x & 31;
    float s = p[l].x, q = p[l].y;
    if (l + 32 < T) { s += p[l+32].x; q += p[l+32].y; }
    #pragma unroll
    for (int o = 16; o > 0; o >>= 1) {
        s += __shfl_xor_sync(0xffffffffu, s, o);
        q += __shfl_xor_sync(0xffffffffu, q, o);
    }
    float m = s * inv_hid;
    float r = rsqrtf(q * inv_hid - m*m + 1e-5f);
    return make_float2(m, r);
}

__device__ __forceinline__ float sigm(float x) { return 1.f / (1.f + expf(-x)); }

__global__ void __launch_bounds__(TPB, 2) k_recur(
    const float* __restrict__ lWi, const float* __restrict__ lbh,
    const float* __restrict__ lWh,
    const float* __restrict__ llig, const float* __restrict__ llib,
    const float* __restrict__ llhg, const float* __restrict__ llhb,
    const float* __restrict__ hWi,  const float* __restrict__ hbi,
    const float* __restrict__ hWh,  const float* __restrict__ hbh,
    const float* __restrict__ hlig, const float* __restrict__ hlib,
    const float* __restrict__ hlhg, const float* __restrict__ hlhb)
{
    __shared__ __align__(16) float As[32*68];
    __shared__ float Ws[32*17];
    __shared__ float s_st[12];

    const float* lWi_h = lWi + (size_t)NE * 3 * NH;  // rows 768..1535 of low_Wi
    int bid = blockIdx.x, tid = threadIdx.x;
    int w = tid >> 5;
    int b = bid & 63, third = bid >> 6;

    for (int t = 0; t < NS; t++) {
        const float* ixt = g_IX + (size_t)t * NB * 3 * NH;
        for (int c = 0; c < 3; c++) {
            // ---- P1: ILOW = h_h @ Wi_h + IX_t  (raw + stats into psA) -------
            gemm_tile(g_hh, NHH, lWi_h, 3*NH, nullptr, ixt,
                      g_ILraw, bid*16, g_psA + (bid>>6)*4096 + (bid & 63), As, Ws);
            gridbar();

            // ---- low-cell inner loop ----------------------------------------
            for (int u = 0; u < 5; u++) {
                // HG = h_l @ Wh + bh (raw + stats into psB)
                gemm_tile(g_hl, NH, lWh, 3*NH, lbh, nullptr,
                          g_HG, bid*16, g_psB + (bid>>6)*4096 + (bid & 63), As, Ws);
                gridbar();

                // combine: LN(IL) + LN(HG) + gates -> h_l
                if (w < 6) {
                    const float2* p = (w < 3)
                        ? g_psA + w*4096 + b*64
                        : g_psB + (w-3)*4096 + b*64;
                    float2 mr = warp_stat(p, 64, 1.f/NH);
                    if ((tid & 31) == 0) { s_st[2*w] = mr.x; s_st[2*w+1] = mr.y; }
                }
                __syncthreads();
                {
                    const float* Ib = g_ILraw + (size_t)b*3*NH;
                    const float* Hb = g_HG    + (size_t)b*3*NH;
                    int js = (third * NH) / 3, je = ((third + 1) * NH) / 3;
                    for (int j = js + tid; j < je; j += TPB) {
                        float i0 = (Ib[j       ] - s_st[0])*s_st[1]*llig[j       ] + llib[j       ];
                        float i1 = (Ib[NH  + j ] - s_st[2])*s_st[3]*llig[NH  + j ] + llib[NH  + j ];
                        float i2 = (Ib[2*NH + j] - s_st[4])*s_st[5]*llig[2*NH + j] + llib[2*NH + j];
                        float h0 = (Hb[j       ] - s_st[6])*s_st[7]*llhg[j       ] + llhb[j       ];
                        float h1 = (Hb[NH  + j ] - s_st[8])*s_st[9]*llhg[NH  + j ] + llhb[NH  + j ];
                        float h2 = (Hb[2*NH + j] - s_st[10])*s_st[11]*llhg[2*NH + j] + llhb[2*NH + j];
                        float r = sigm(i0 + h0);
                        float z = sigm(i1 + h1);
                        float n = tanhf(i2 + r*h2);
                        float hp = g_hl[(size_t)b*NH + j];
                        g_hl[(size_t)b*NH + j] = (1.f - z)*n + z*hp;
                    }
                }
                gridbar();
            }

            // ---- P5: high-cell GEMMs (288 tile jobs over 192 blocks) --------
            for (int job = bid; job < 288; job += GRID) {
                if (job < 144) {
                    gemm_tile(g_hl, NH, hWi, 3*NHH, hbi, nullptr,
                              g_IHI, job*16, g_psA + (job/48)*4096 + (job%48), As, Ws);
                } else {
                    int nt = job - 144;
                    gemm_tile(g_hh, NHH, hWh, 3*NHH, hbh, nullptr,
                              g_HHG, nt*16, g_psB + (nt/48)*4096 + (nt%48), As, Ws);
                }
            }
            gridbar();

            // ---- P6: high combine -> h_h (+history at c==2) ------------------
            if (w < 6) {
                const float2* p = (w < 3)
                    ? g_psA + w*4096 + b*64
                    : g_psB + (w-3)*4096 + b*64;
                float2 mr = warp_stat(p, 48, 1.f/NHH);
                if ((tid & 31) == 0) { s_st[2*w] = mr.x; s_st[2*w+1] = mr.y; }
            }
            __syncthreads();
            {
                const float* Ib = g_IHI + (size_t)b*3*NHH;
                const float* Hb = g_HHG + (size_t)b*3*NHH;
                int j = third*256 + tid;   // exactly covers 0..767
                float i0 = (Ib[j        ] - s_st[0])*s_st[1]*hlig[j        ] + hlib[j        ];
                float i1 = (Ib[NHH  + j ] - s_st[2])*s_st[3]*hlig[NHH  + j ] + hlib[NHH  + j ];
                float i2 = (Ib[2*NHH + j] - s_st[4])*s_st[5]*hlig[2*NHH + j] + hlib[2*NHH + j];
                float h0 = (Hb[j        ] - s_st[6])*s_st[7]*hlhg[j        ] + hlhb[j        ];
                float h1 = (Hb[NHH  + j ] - s_st[8])*s_st[9]*hlhg[NHH  + j ] + hlhb[NHH  + j ];
                float h2 = (Hb[2*NHH + j] - s_st[10])*s_st[11]*hlhg[2*NHH + j] + hlhb[2*NHH + j];
                float r = sigm(i0 + h0);
                float z = sigm(i1 + h1);
                float n = tanhf(i2 + r*h2);
                float hp = g_hh[(size_t)b*NHH + j];
                float nv = (1.f - z)*n + z*hp;
                g_hh[(size_t)b*NHH + j] = nv;
                if (c == 2) g_HH[(size_t)(t*64 + b)*NHH + j] = nv;
            }
            gridbar();
        }
    }
}

// ---------------- host orchestration ----------------------------------------
extern "C" void kernel_launch(void* const* d_in, const int* in_sizes, int n_in,
                              void* d_out, int out_size) {
    const int*   ids  = (const int*)  d_in[0];
    const float* emb  = (const float*)d_in[1];
    const float* leg  = (const float*)d_in[2];
    const float* leb  = (const float*)d_in[3];
    const float* lWi  = (const float*)d_in[4];   // [1536, 3072]
    const float* lbi  = (const float*)d_in[5];
    const float* lWh  = (const float*)d_in[6];   // [1024, 3072]
    const float* lbh  = (const float*)d_in[7];
    const float* llig = (const float*)d_in[8];
    const float* llib = (const float*)d_in[9];
    const float* llhg = (const float*)d_in[10];
    const float* llhb = (const float*)d_in[11];
    const float* hWi  = (const float*)d_in[12];  // [1024, 2304]
    const float* hbi  = (const float*)d_in[13];
    const float* hWh  = (const float*)d_in[14];  // [768, 2304]
    const float* hbh  = (const float*)d_in[15];
    const float* hlig = (const float*)d_in[16];
    const float* hlib = (const float*)d_in[17];
    const float* hlhg = (const float*)d_in[18];
    const float* hlhb = (const float*)d_in[19];
    const float* Wout = (const float*)d_in[20];  // [768, 32000]
    const float* bout = (const float*)d_in[21];
    float* out = (float*)d_out;

    float *pX, *pIX, *pHH;
    cudaGetSymbolAddress((void**)&pX,  g_X);
    cudaGetSymbolAddress((void**)&pIX, g_IX);
    cudaGetSymbolAddress((void**)&pHH, g_HH);

    // zero hidden states
    k_init<<<256, 256>>>();

    // x = LN(emb[ids]) laid out [S, B, E]
    k_embed<<<NB*NS, 256>>>(ids, emb, leg, leb);

    // IX = x @ Wi_x + bi for ALL tokens up front (reused 15x per step)
    k_gemm_n64<<<dim3((3*NH)/64, (NB*NS)/64), 256>>>(pX, lWi, lbi, pIX, NE, 3*NH, 0);

    // full recurrence in ONE persistent kernel (software grid barriers)
    k_recur<<<GRID, TPB>>>(lWi, lbh, lWh,
                           llig, llib, llhg, llhb,
                           hWi, hbi, hWh, hbh,
                           hlig, hlib, hlhg, hlhb);

    // logits = h_h_hist @ Wout + bout, row remap (s*64+b) -> out[(b*64+s)*V]
    k_gemm_n64<<<dim3(NV/64, (NB*NS)/64), 256>>>(pHH, Wout, bout, out, NHH, NV, 1);
}